// round 13
// baseline (speedup 1.0000x reference)
#include <cuda_runtime.h>
#include <math.h>

#define NN 50000
#define EE 800000
#define NF0 128
#define NF1 64
#define NF2 40
#define NCH 49        /* ceil(NN/1024) */

// ---------------- scratch (__device__ globals; allocation-free) ----------------
// Device globals are zero-initialized at module load. g_deg/g_cur are re-zeroed
// at the END of each kernel_launch (tail of k_spmm40_lsm).
__device__ __align__(256) float g_P0[NN * NF0];   // M ⊙ (x @ W0)
__device__ __align__(256) float g_S0[NN * NF0];   // H0 = relu(AM⊙spmm + b0)
__device__ __align__(256) float g_P1[NN * NF1];   // M ⊙ (H0 @ W1)
__device__ __align__(256) float g_P2[NN * NF2];   // H1 @ W2
__device__ __align__(256) int   g_rp[NN + 1];
__device__ __align__(256) int   g_deg[NN];
__device__ __align__(256) int   g_cur[NN];
__device__ __align__(256) int   g_colP[EE];
__device__ __align__(256) float g_vZ[EE];
__device__ __align__(256) float g_vA[EE];
__device__ __align__(256) int   g_part[NCH];

// ---------------- helpers ----------------
__device__ __forceinline__ unsigned f2tf(float f) {
    unsigned u;
    asm("cvt.rna.tf32.f32 %0, %1;" : "=r"(u) : "f"(f));
    return u;
}

__device__ __forceinline__ void mma_tf32(float c[4],
                                         const unsigned a[4],
                                         const unsigned b[2]) {
    asm volatile(
        "mma.sync.aligned.m16n8k8.row.col.f32.tf32.tf32.f32 "
        "{%0,%1,%2,%3}, {%4,%5,%6,%7}, {%8,%9}, {%0,%1,%2,%3};"
        : "+f"(c[0]), "+f"(c[1]), "+f"(c[2]), "+f"(c[3])
        : "r"(a[0]), "r"(a[1]), "r"(a[2]), "r"(a[3]), "r"(b[0]), "r"(b[1]));
}

__device__ __forceinline__ void cp_async16(void* smem_dst, const void* gsrc, int src_bytes) {
    unsigned d = (unsigned)__cvta_generic_to_shared(smem_dst);
    asm volatile("cp.async.cg.shared.global [%0], [%1], 16, %2;"
                 :: "r"(d), "l"(gsrc), "r"(src_bytes));
}
__device__ __forceinline__ void cp_commit() { asm volatile("cp.async.commit_group;"); }
__device__ __forceinline__ void cp_wait0()  { asm volatile("cp.async.wait_group 0;"); }

// ---------------- CSR build ----------------
__global__ void k_hist(const int* __restrict__ row) {
    int e = blockIdx.x * blockDim.x + threadIdx.x;
    if (e < EE) atomicAdd(&g_deg[row[e]], 1);
}

__global__ void k_scan1() {   // per-chunk sums (chunk = 1024)
    __shared__ int sred[8];
    int base = blockIdx.x * 1024;
    int local = 0;
    #pragma unroll
    for (int j = 0; j < 4; ++j) {
        int i = base + threadIdx.x + j * 256;
        if (i < NN) local += g_deg[i];
    }
    for (int off = 16; off; off >>= 1) local += __shfl_down_sync(0xffffffffu, local, off);
    if ((threadIdx.x & 31) == 0) sred[threadIdx.x >> 5] = local;
    __syncthreads();
    if (threadIdx.x == 0) {
        int s = 0;
        #pragma unroll
        for (int w = 0; w < 8; ++w) s += sred[w];
        g_part[blockIdx.x] = s;
    }
}

// fused scan2+scan3: each block computes its chunk offset then in-chunk scan.
__global__ void k_scan23() {
    __shared__ int s[1024];
    __shared__ int psum[2];
    int bid = blockIdx.x;
    int tid = threadIdx.x;
    int i = bid * 1024 + tid;
    int v = (i < NN) ? g_deg[i] : 0;
    s[tid] = v;
    if (tid < 64) {
        int p = (tid < bid) ? g_part[tid] : 0;   // bid <= 48 < 64
        for (int off = 16; off; off >>= 1) p += __shfl_down_sync(0xffffffffu, p, off);
        if ((tid & 31) == 0) psum[tid >> 5] = p;
    }
    __syncthreads();
    int off0 = psum[0] + psum[1];
    for (int off = 1; off < 1024; off <<= 1) {
        int t = (tid >= (unsigned)off) ? s[tid - off] : 0;
        __syncthreads();
        s[tid] += t;
        __syncthreads();
    }
    if (i < NN) g_rp[i] = off0 + s[tid] - v;
    if (bid == 0 && tid == 0) g_rp[NN] = EE;
}

// standalone scatter — zero smem, low regs, full occupancy to hide atomic +
// random-store latency (fusing this into gemm0 throttled it to 2 CTA/SM).
__global__ void k_scatter(const int* __restrict__ row, const int* __restrict__ col,
                          const float* __restrict__ vZ, const float* __restrict__ vA) {
    int e = blockIdx.x * blockDim.x + threadIdx.x;
    if (e >= EE) return;
    int r = row[e];
    int pos = g_rp[r] + atomicAdd(&g_cur[r], 1);
    g_colP[pos] = col[e];
    g_vZ[pos]   = vZ[e];
    g_vA[pos]   = vA[e];
}

// ======== GEMM 0 (tf32, cp.async double-buffered): P0 = M ⊙ (x @ W0) ========
// 50000x128x128. Block tile 128x128, 256 threads (8 warps 2m x 4n), warp 64x32.
#define KCH 16
__global__ void __launch_bounds__(256, 2) k_gemm0(const float* __restrict__ x,
                                                  const float* __restrict__ W0,
                                                  const float* __restrict__ M) {
    __shared__ __align__(16) float As[2][128 * 20];   // [m][k], pad-20 (conflict-free)
    __shared__ __align__(16) float Bs[2][KCH * 128];  // [k][n ^ ((k&3)<<3)]
    int r0 = blockIdx.x * 128;
    int tid = threadIdx.x;
    int lane = tid & 31, wid = tid >> 5;
    int m0w = (wid & 1) * 64;
    int n0w = (wid >> 1) * 32;
    int g = lane >> 2, t = lane & 3;

    float acc[4][4][4];
    #pragma unroll
    for (int i = 0; i < 4; ++i)
        #pragma unroll
        for (int j = 0; j < 4; ++j)
            #pragma unroll
            for (int c = 0; c < 4; ++c) acc[i][j][c] = 0.f;

    const float4* xv = (const float4*)x;
    const float4* wv = (const float4*)W0;

    int a_rr = tid >> 2, a_c4 = tid & 3;
    int b_kr = tid >> 5, b_c4 = tid & 31;

#define STAGE0(kc, buf)                                                          \
    {                                                                            \
        int _gr0 = r0 + a_rr;                                                    \
        int _gr1 = _gr0 + 64;                                                    \
        cp_async16(&As[buf][a_rr * 20 + a_c4 * 4],                               \
                   xv + (long)_gr0 * 32 + ((kc) >> 2) + a_c4,                    \
                   _gr0 < NN ? 16 : 0);                                          \
        cp_async16(&As[buf][(a_rr + 64) * 20 + a_c4 * 4],                        \
                   xv + (long)_gr1 * 32 + ((kc) >> 2) + a_c4,                    \
                   _gr1 < NN ? 16 : 0);                                          \
        cp_async16(&Bs[buf][b_kr * 128 + ((b_c4 * 4) ^ ((b_kr & 3) << 3))],      \
                   wv + ((kc) + b_kr) * 32 + b_c4, 16);                          \
        cp_async16(&Bs[buf][(b_kr + 8) * 128 + ((b_c4 * 4) ^ ((b_kr & 3) << 3))],\
                   wv + ((kc) + b_kr + 8) * 32 + b_c4, 16);                      \
        cp_commit();                                                             \
    }

    STAGE0(0, 0);
    cp_wait0();
    __syncthreads();

    int buf = 0;
    for (int kc = 0; kc < 128; kc += KCH, buf ^= 1) {
        if (kc + KCH < 128) STAGE0(kc + KCH, buf ^ 1);
        #pragma unroll
        for (int k8 = 0; k8 < KCH; k8 += 8) {
            unsigned af[4][4], bf[4][2];
            #pragma unroll
            for (int mt = 0; mt < 4; ++mt) {
                int m = m0w + mt * 16 + g;
                af[mt][0] = f2tf(As[buf][m * 20 + k8 + t]);
                af[mt][1] = f2tf(As[buf][(m + 8) * 20 + k8 + t]);
                af[mt][2] = f2tf(As[buf][m * 20 + k8 + t + 4]);
                af[mt][3] = f2tf(As[buf][(m + 8) * 20 + k8 + t + 4]);
            }
            #pragma unroll
            for (int nt = 0; nt < 4; ++nt) {
                int n = n0w + nt * 8 + g;
                bf[nt][0] = f2tf(Bs[buf][(k8 + t) * 128 + (n ^ (t << 3))]);
                bf[nt][1] = f2tf(Bs[buf][(k8 + t + 4) * 128 + (n ^ (t << 3))]);
            }
            #pragma unroll
            for (int mt = 0; mt < 4; ++mt)
                #pragma unroll
                for (int nt = 0; nt < 4; ++nt)
                    mma_tf32(acc[mt][nt], af[mt], bf[nt]);
        }
        if (kc + KCH < 128) cp_wait0();
        __syncthreads();
    }

    #pragma unroll
    for (int mt = 0; mt < 4; ++mt) {
        int rlo = r0 + m0w + mt * 16 + g;
        int rhi = rlo + 8;
        float mlo = (rlo < NN) ? M[rlo] : 0.f;
        float mhi = (rhi < NN) ? M[rhi] : 0.f;
        #pragma unroll
        for (int nt = 0; nt < 4; ++nt) {
            int cc = n0w + nt * 8 + 2 * t;
            if (rlo < NN) {
                float2 o; o.x = mlo * acc[mt][nt][0]; o.y = mlo * acc[mt][nt][1];
                *(float2*)&g_P0[rlo * 128 + cc] = o;
            }
            if (rhi < NN) {
                float2 o; o.x = mhi * acc[mt][nt][2]; o.y = mhi * acc[mt][nt][3];
                *(float2*)&g_P0[rhi * 128 + cc] = o;
            }
        }
    }
}
#undef STAGE0
#undef KCH

// -- spmm width 128 + fused relu(AM⊙s + b0): H0 -> g_S0 --
__global__ void __launch_bounds__(256) k_spmm128(const float* __restrict__ AM,
                                                 const float* __restrict__ b0) {
    int w = (blockIdx.x * 256 + threadIdx.x) >> 5;
    int lane = threadIdx.x & 31;
    if (w >= NN) return;
    int s = g_rp[w], e = g_rp[w + 1];
    float4 acc = make_float4(0.f, 0.f, 0.f, 0.f);
    const float4* Xv = (const float4*)g_P0;
    int j = s;
    for (; j + 1 < e; j += 2) {
        int c0 = g_colP[j], c1 = g_colP[j + 1];
        float v0 = g_vZ[j], v1 = g_vZ[j + 1];
        float4 a = Xv[c0 * 32 + lane];
        float4 b = Xv[c1 * 32 + lane];
        acc.x += v0 * a.x + v1 * b.x;
        acc.y += v0 * a.y + v1 * b.y;
        acc.z += v0 * a.z + v1 * b.z;
        acc.w += v0 * a.w + v1 * b.w;
    }
    if (j < e) {
        int c = g_colP[j]; float v = g_vZ[j];
        float4 a = Xv[c * 32 + lane];
        acc.x += v * a.x; acc.y += v * a.y; acc.z += v * a.z; acc.w += v * a.w;
    }
    float am = AM[w];
    float4 bb = ((const float4*)b0)[lane];
    float4 o;
    o.x = fmaxf(fmaf(am, acc.x, bb.x), 0.f);
    o.y = fmaxf(fmaf(am, acc.y, bb.y), 0.f);
    o.z = fmaxf(fmaf(am, acc.z, bb.z), 0.f);
    o.w = fmaxf(fmaf(am, acc.w, bb.w), 0.f);
    ((float4*)g_S0)[w * 32 + lane] = o;
}

// ======== GEMM 1 (tf32, cp.async double-buffered): P1 = M ⊙ (H0 @ W1) ========
#define KCH1 16
__global__ void __launch_bounds__(256, 2) k_gemm1(const float* __restrict__ W1,
                                                  const float* __restrict__ M) {
    __shared__ __align__(16) float As[2][128 * 20];
    __shared__ __align__(16) float Bs[2][KCH1 * 64];
    int r0 = blockIdx.x * 128;
    int tid = threadIdx.x;
    int lane = tid & 31, wid = tid >> 5;
    int m0w = (wid & 3) * 32;
    int n0w = (wid >> 2) * 32;
    int g = lane >> 2, t = lane & 3;

    float acc[2][4][4];
    #pragma unroll
    for (int i = 0; i < 2; ++i)
        #pragma unroll
        for (int j = 0; j < 4; ++j)
            #pragma unroll
            for (int c = 0; c < 4; ++c) acc[i][j][c] = 0.f;

    const float4* hv = (const float4*)g_S0;
    const float4* wv = (const float4*)W1;

    int a_rr = tid >> 2, a_c4 = tid & 3;
    int b_kr = tid >> 4, b_c4 = tid & 15;

#define STAGE1(kc, buf)                                                          \
    {                                                                            \
        int _gr0 = r0 + a_rr;                                                    \
        int _gr1 = _gr0 + 64;                                                    \
        cp_async16(&As[buf][a_rr * 20 + a_c4 * 4],                               \
                   hv + (long)_gr0 * 32 + ((kc) >> 2) + a_c4,                    \
                   _gr0 < NN ? 16 : 0);                                          \
        cp_async16(&As[buf][(a_rr + 64) * 20 + a_c4 * 4],                        \
                   hv + (long)_gr1 * 32 + ((kc) >> 2) + a_c4,                    \
                   _gr1 < NN ? 16 : 0);                                          \
        cp_async16(&Bs[buf][b_kr * 64 + ((b_c4 * 4) ^ ((b_kr & 3) << 3))],       \
                   wv + ((kc) + b_kr) * 16 + b_c4, 16);                          \
        cp_commit();                                                             \
    }

    STAGE1(0, 0);
    cp_wait0();
    __syncthreads();

    int buf = 0;
    for (int kc = 0; kc < 128; kc += KCH1, buf ^= 1) {
        if (kc + KCH1 < 128) STAGE1(kc + KCH1, buf ^ 1);
        #pragma unroll
        for (int k8 = 0; k8 < KCH1; k8 += 8) {
            unsigned af[2][4], bf[4][2];
            #pragma unroll
            for (int mt = 0; mt < 2; ++mt) {
                int m = m0w + mt * 16 + g;
                af[mt][0] = f2tf(As[buf][m * 20 + k8 + t]);
                af[mt][1] = f2tf(As[buf][(m + 8) * 20 + k8 + t]);
                af[mt][2] = f2tf(As[buf][m * 20 + k8 + t + 4]);
                af[mt][3] = f2tf(As[buf][(m + 8) * 20 + k8 + t + 4]);
            }
            #pragma unroll
            for (int nt = 0; nt < 4; ++nt) {
                int n = n0w + nt * 8 + g;
                bf[nt][0] = f2tf(Bs[buf][(k8 + t) * 64 + (n ^ (t << 3))]);
                bf[nt][1] = f2tf(Bs[buf][(k8 + t + 4) * 64 + (n ^ (t << 3))]);
            }
            #pragma unroll
            for (int mt = 0; mt < 2; ++mt)
                #pragma unroll
                for (int nt = 0; nt < 4; ++nt)
                    mma_tf32(acc[mt][nt], af[mt], bf[nt]);
        }
        if (kc + KCH1 < 128) cp_wait0();
        __syncthreads();
    }

    #pragma unroll
    for (int mt = 0; mt < 2; ++mt) {
        int rlo = r0 + m0w + mt * 16 + g;
        int rhi = rlo + 8;
        float mlo = (rlo < NN) ? M[rlo] : 0.f;
        float mhi = (rhi < NN) ? M[rhi] : 0.f;
        #pragma unroll
        for (int nt = 0; nt < 4; ++nt) {
            int cc = n0w + nt * 8 + 2 * t;
            if (rlo < NN) {
                float2 o; o.x = mlo * acc[mt][nt][0]; o.y = mlo * acc[mt][nt][1];
                *(float2*)&g_P1[rlo * 64 + cc] = o;
            }
            if (rhi < NN) {
                float2 o; o.x = mhi * acc[mt][nt][2]; o.y = mhi * acc[mt][nt][3];
                *(float2*)&g_P1[rhi * 64 + cc] = o;
            }
        }
    }
}
#undef STAGE1
#undef KCH1

// ==== FUSED: spmm64 + relu(AM⊙s+b1) + gemm2 (H1row @ W2) -> g_P2 ====
// Each warp: gather its H1 row (64 wide), stash in smem, then lanes 0..19
// each compute 2 of the 40 P2 outputs from smem-resident W2.
__global__ void __launch_bounds__(256) k_spmm64g2(const float* __restrict__ AM,
                                                  const float* __restrict__ b1,
                                                  const float* __restrict__ W2) {
    __shared__ float Ws[64 * 40];     // 10 KB
    __shared__ float Hrow[8][64];     // 2 KB, one row per warp
    int tid = threadIdx.x;
    for (int i = tid; i < 64 * 40; i += 256) Ws[i] = W2[i];

    int w = (blockIdx.x * 256 + tid) >> 5;
    int lane = tid & 31;
    int wl = tid >> 5;
    bool valid = (w < NN);

    if (valid) {
        int s = g_rp[w], e = g_rp[w + 1];
        float ax = 0.f, ay = 0.f;
        const float2* Xv = (const float2*)g_P1;
        int j = s;
        for (; j + 1 < e; j += 2) {
            int c0 = g_colP[j], c1 = g_colP[j + 1];
            float v0 = g_vZ[j], v1 = g_vZ[j + 1];
            float2 a = Xv[c0 * 32 + lane];
            float2 b = Xv[c1 * 32 + lane];
            ax += v0 * a.x + v1 * b.x;
            ay += v0 * a.y + v1 * b.y;
        }
        if (j < e) {
            int c = g_colP[j]; float v = g_vZ[j];
            float2 a = Xv[c * 32 + lane];
            ax += v * a.x; ay += v * a.y;
        }
        float am = AM[w];
        float2 bb = ((const float2*)b1)[lane];
        float2 h;
        h.x = fmaxf(fmaf(am, ax, bb.x), 0.f);
        h.y = fmaxf(fmaf(am, ay, bb.y), 0.f);
        *(float2*)&Hrow[wl][2 * lane] = h;
    }
    __syncthreads();   // covers Ws load + all Hrow writes

    if (valid && lane < 20) {
        float2 acc = make_float2(0.f, 0.f);
        #pragma unroll 8
        for (int k = 0; k < 64; ++k) {
            float h = Hrow[wl][k];                       // broadcast
            float2 wv = *(const float2*)&Ws[k * 40 + 2 * lane];
            acc.x += h * wv.x;
            acc.y += h * wv.y;
        }
        *(float2*)&g_P2[w * 40 + 2 * lane] = acc;
    }
}

// -- spmm width 40 on adj + b2 + fused log_softmax -> out; re-zeros g_deg/g_cur --
__global__ void __launch_bounds__(256) k_spmm40_lsm(const float* __restrict__ b2,
                                                    float* __restrict__ out) {
    int gi = blockIdx.x * 256 + threadIdx.x;
    if (gi < NN) { g_deg[gi] = 0; g_cur[gi] = 0; }   // cleanup for next call/replay
    int w = gi >> 5;
    int lane = threadIdx.x & 31;
    if (w >= NN) return;
    int s = g_rp[w], e = g_rp[w + 1];
    bool act = lane < 20;
    float ax = 0.f, ay = 0.f;
    int j = s;
    for (; j + 1 < e; j += 2) {
        int c0 = g_colP[j], c1 = g_colP[j + 1];
        float v0 = g_vA[j], v1 = g_vA[j + 1];
        if (act) {
            float2 a = *(const float2*)&g_P2[c0 * 40 + 2 * lane];
            float2 b = *(const float2*)&g_P2[c1 * 40 + 2 * lane];
            ax += v0 * a.x + v1 * b.x;
            ay += v0 * a.y + v1 * b.y;
        }
    }
    if (j < e) {
        int c = g_colP[j];
        float v = g_vA[j];
        if (act) {
            float2 a = *(const float2*)&g_P2[c * 40 + 2 * lane];
            ax += v * a.x;
            ay += v * a.y;
        }
    }
    if (act) {
        ax += b2[2 * lane];
        ay += b2[2 * lane + 1];
    }
    float m = act ? fmaxf(ax, ay) : -INFINITY;
    for (int off = 16; off; off >>= 1) m = fmaxf(m, __shfl_xor_sync(0xffffffffu, m, off));
    float sum = act ? (expf(ax - m) + expf(ay - m)) : 0.f;
    for (int off = 16; off; off >>= 1) sum += __shfl_xor_sync(0xffffffffu, sum, off);
    float lse = m + logf(sum);
    if (act) {
        float2 o;
        o.x = ax - lse;
        o.y = ay - lse;
        *(float2*)&out[w * 40 + 2 * lane] = o;
    }
}

// ---------------- launch ----------------
extern "C" void kernel_launch(void* const* d_in, const int* in_sizes, int n_in,
                              void* d_out, int out_size) {
    const float* x    = (const float*)d_in[0];
    const float* M    = (const float*)d_in[1];
    const float* AM   = (const float*)d_in[2];
    const float* adjv = (const float*)d_in[3];
    const float* adjZ = (const float*)d_in[4];
    const float* W0   = (const float*)d_in[5];
    const float* b0   = (const float*)d_in[6];
    const float* W1   = (const float*)d_in[7];
    const float* b1   = (const float*)d_in[8];
    const float* W2   = (const float*)d_in[9];
    const float* b2   = (const float*)d_in[10];
    const int*   row  = (const int*)d_in[11];
    const int*   col  = (const int*)d_in[12];
    float* out = (float*)d_out;

    (void)in_sizes; (void)n_in; (void)out_size;

    // 9 launches. Slot 4 (ncu capture window) = k_scatter this round.
    k_hist<<<(EE + 255) / 256, 256>>>(row);
    k_scan1<<<NCH, 256>>>();
    k_scan23<<<NCH, 1024>>>();
    k_scatter<<<(EE + 255) / 256, 256>>>(row, col, adjZ, adjv);   // 4th launch
    k_gemm0<<<(NN + 127) / 128, 256>>>(x, W0, M);

    k_spmm128<<<(NN + 7) / 8, 256>>>(AM, b0);
    k_gemm1<<<(NN + 127) / 128, 256>>>(W1, M);
    k_spmm64g2<<<(NN + 7) / 8, 256>>>(AM, b1, W2);
    k_spmm40_lsm<<<(NN + 7) / 8, 256>>>(b2, out);
}

// round 16
// speedup vs baseline: 1.0482x; 1.0482x over previous
#include <cuda_runtime.h>
#include <math.h>

#define NN 50000
#define EE 800000
#define NF0 128
#define NF1 64
#define NF2 40
#define NCH 49        /* ceil(NN/1024) */

// ---------------- scratch (__device__ globals; allocation-free) ----------------
// Device globals are zero-initialized at module load. g_deg is re-zeroed at the
// END of each kernel_launch (tail of k_spmm40_lsm). g_cur is rewritten by
// k_scan23 every call (serves as the scatter cursor).
__device__ __align__(256) float g_P0[NN * NF0];   // M ⊙ (x @ W0)
__device__ __align__(256) float g_S0[NN * NF0];   // H0 = relu(AM⊙spmm + b0)
__device__ __align__(256) float g_P1[NN * NF1];   // M ⊙ (H0 @ W1)
__device__ __align__(256) float g_S1[NN * NF1];   // H1 = relu(AM⊙spmm + b1)
__device__ __align__(256) float g_P2[NN * NF2];   // H1 @ W2
__device__ __align__(256) int   g_rp[NN + 1];
__device__ __align__(256) int   g_deg[NN];
__device__ __align__(256) int   g_cur[NN];        // scatter cursor (= rp, bumped)
__device__ __align__(256) int   g_colP[EE];
__device__ __align__(256) float g_vZ[EE];
__device__ __align__(256) float g_vA[EE];
__device__ __align__(256) int   g_part[NCH];

// ---------------- helpers ----------------
__device__ __forceinline__ unsigned f2tf(float f) {
    unsigned u;
    asm("cvt.rna.tf32.f32 %0, %1;" : "=r"(u) : "f"(f));
    return u;
}

__device__ __forceinline__ void mma_tf32(float c[4],
                                         const unsigned a[4],
                                         const unsigned b[2]) {
    asm volatile(
        "mma.sync.aligned.m16n8k8.row.col.f32.tf32.tf32.f32 "
        "{%0,%1,%2,%3}, {%4,%5,%6,%7}, {%8,%9}, {%0,%1,%2,%3};"
        : "+f"(c[0]), "+f"(c[1]), "+f"(c[2]), "+f"(c[3])
        : "r"(a[0]), "r"(a[1]), "r"(a[2]), "r"(a[3]), "r"(b[0]), "r"(b[1]));
}

__device__ __forceinline__ void cp_async16(void* smem_dst, const void* gsrc, int src_bytes) {
    unsigned d = (unsigned)__cvta_generic_to_shared(smem_dst);
    asm volatile("cp.async.cg.shared.global [%0], [%1], 16, %2;"
                 :: "r"(d), "l"(gsrc), "r"(src_bytes));
}
__device__ __forceinline__ void cp_commit() { asm volatile("cp.async.commit_group;"); }
__device__ __forceinline__ void cp_wait0()  { asm volatile("cp.async.wait_group 0;"); }

// ---------------- CSR build ----------------
__global__ void k_hist(const int* __restrict__ row) {
    int e = blockIdx.x * blockDim.x + threadIdx.x;
    if (e < EE) atomicAdd(&g_deg[row[e]], 1);
}

__global__ void k_scan1() {   // per-chunk sums (chunk = 1024)
    __shared__ int sred[8];
    int base = blockIdx.x * 1024;
    int local = 0;
    #pragma unroll
    for (int j = 0; j < 4; ++j) {
        int i = base + threadIdx.x + j * 256;
        if (i < NN) local += g_deg[i];
    }
    for (int off = 16; off; off >>= 1) local += __shfl_down_sync(0xffffffffu, local, off);
    if ((threadIdx.x & 31) == 0) sred[threadIdx.x >> 5] = local;
    __syncthreads();
    if (threadIdx.x == 0) {
        int s = 0;
        #pragma unroll
        for (int w = 0; w < 8; ++w) s += sred[w];
        g_part[blockIdx.x] = s;
    }
}

// fused scan2+scan3; also seeds the scatter cursor g_cur = rp.
__global__ void k_scan23() {
    __shared__ int s[1024];
    __shared__ int psum[2];
    int bid = blockIdx.x;
    int tid = threadIdx.x;
    int i = bid * 1024 + tid;
    int v = (i < NN) ? g_deg[i] : 0;
    s[tid] = v;
    if (tid < 64) {
        int p = (tid < bid) ? g_part[tid] : 0;   // bid <= 48 < 64
        for (int off = 16; off; off >>= 1) p += __shfl_down_sync(0xffffffffu, p, off);
        if ((tid & 31) == 0) psum[tid >> 5] = p;
    }
    __syncthreads();
    int off0 = psum[0] + psum[1];
    for (int off = 1; off < 1024; off <<= 1) {
        int t = (tid >= (unsigned)off) ? s[tid - off] : 0;
        __syncthreads();
        s[tid] += t;
        __syncthreads();
    }
    if (i < NN) {
        int rp = off0 + s[tid] - v;
        g_rp[i]  = rp;
        g_cur[i] = rp;      // cursor seed — scatter atomics bump this directly
    }
    if (bid == 0 && tid == 0) g_rp[NN] = EE;
}

// scatter: per edge = 1 atomic (pre-seeded cursor) + 3 stores. Standalone for
// full occupancy (fusing into gemm0 throttled it to 2 CTA/SM).
__global__ void k_scatter(const int* __restrict__ row, const int* __restrict__ col,
                          const float* __restrict__ vZ, const float* __restrict__ vA) {
    int e = blockIdx.x * blockDim.x + threadIdx.x;
    if (e >= EE) return;
    int r = row[e];
    int pos = atomicAdd(&g_cur[r], 1);
    g_colP[pos] = col[e];
    g_vZ[pos]   = vZ[e];
    g_vA[pos]   = vA[e];
}

// ======== GEMM 0 (tf32, cp.async double-buffered): P0 = M ⊙ (x @ W0) ========
// 50000x128x128. Block tile 128x128, 256 threads (8 warps 2m x 4n), warp 64x32.
#define KCH 16
__global__ void __launch_bounds__(256, 2) k_gemm0(const float* __restrict__ x,
                                                  const float* __restrict__ W0,
                                                  const float* __restrict__ M) {
    __shared__ __align__(16) float As[2][128 * 20];   // [m][k], pad-20 (conflict-free)
    __shared__ __align__(16) float Bs[2][KCH * 128];  // [k][n ^ ((k&3)<<3)]
    int r0 = blockIdx.x * 128;
    int tid = threadIdx.x;
    int lane = tid & 31, wid = tid >> 5;
    int m0w = (wid & 1) * 64;
    int n0w = (wid >> 1) * 32;
    int g = lane >> 2, t = lane & 3;

    float acc[4][4][4];
    #pragma unroll
    for (int i = 0; i < 4; ++i)
        #pragma unroll
        for (int j = 0; j < 4; ++j)
            #pragma unroll
            for (int c = 0; c < 4; ++c) acc[i][j][c] = 0.f;

    const float4* xv = (const float4*)x;
    const float4* wv = (const float4*)W0;

    int a_rr = tid >> 2, a_c4 = tid & 3;
    int b_kr = tid >> 5, b_c4 = tid & 31;

#define STAGE0(kc, buf)                                                          \
    {                                                                            \
        int _gr0 = r0 + a_rr;                                                    \
        int _gr1 = _gr0 + 64;                                                    \
        cp_async16(&As[buf][a_rr * 20 + a_c4 * 4],                               \
                   xv + (long)_gr0 * 32 + ((kc) >> 2) + a_c4,                    \
                   _gr0 < NN ? 16 : 0);                                          \
        cp_async16(&As[buf][(a_rr + 64) * 20 + a_c4 * 4],                        \
                   xv + (long)_gr1 * 32 + ((kc) >> 2) + a_c4,                    \
                   _gr1 < NN ? 16 : 0);                                          \
        cp_async16(&Bs[buf][b_kr * 128 + ((b_c4 * 4) ^ ((b_kr & 3) << 3))],      \
                   wv + ((kc) + b_kr) * 32 + b_c4, 16);                          \
        cp_async16(&Bs[buf][(b_kr + 8) * 128 + ((b_c4 * 4) ^ ((b_kr & 3) << 3))],\
                   wv + ((kc) + b_kr + 8) * 32 + b_c4, 16);                      \
        cp_commit();                                                             \
    }

    STAGE0(0, 0);
    cp_wait0();
    __syncthreads();

    int buf = 0;
    for (int kc = 0; kc < 128; kc += KCH, buf ^= 1) {
        if (kc + KCH < 128) STAGE0(kc + KCH, buf ^ 1);
        #pragma unroll
        for (int k8 = 0; k8 < KCH; k8 += 8) {
            unsigned af[4][4], bf[4][2];
            #pragma unroll
            for (int mt = 0; mt < 4; ++mt) {
                int m = m0w + mt * 16 + g;
                af[mt][0] = f2tf(As[buf][m * 20 + k8 + t]);
                af[mt][1] = f2tf(As[buf][(m + 8) * 20 + k8 + t]);
                af[mt][2] = f2tf(As[buf][m * 20 + k8 + t + 4]);
                af[mt][3] = f2tf(As[buf][(m + 8) * 20 + k8 + t + 4]);
            }
            #pragma unroll
            for (int nt = 0; nt < 4; ++nt) {
                int n = n0w + nt * 8 + g;
                bf[nt][0] = f2tf(Bs[buf][(k8 + t) * 128 + (n ^ (t << 3))]);
                bf[nt][1] = f2tf(Bs[buf][(k8 + t + 4) * 128 + (n ^ (t << 3))]);
            }
            #pragma unroll
            for (int mt = 0; mt < 4; ++mt)
                #pragma unroll
                for (int nt = 0; nt < 4; ++nt)
                    mma_tf32(acc[mt][nt], af[mt], bf[nt]);
        }
        if (kc + KCH < 128) cp_wait0();
        __syncthreads();
    }

    #pragma unroll
    for (int mt = 0; mt < 4; ++mt) {
        int rlo = r0 + m0w + mt * 16 + g;
        int rhi = rlo + 8;
        float mlo = (rlo < NN) ? M[rlo] : 0.f;
        float mhi = (rhi < NN) ? M[rhi] : 0.f;
        #pragma unroll
        for (int nt = 0; nt < 4; ++nt) {
            int cc = n0w + nt * 8 + 2 * t;
            if (rlo < NN) {
                float2 o; o.x = mlo * acc[mt][nt][0]; o.y = mlo * acc[mt][nt][1];
                *(float2*)&g_P0[rlo * 128 + cc] = o;
            }
            if (rhi < NN) {
                float2 o; o.x = mhi * acc[mt][nt][2]; o.y = mhi * acc[mt][nt][3];
                *(float2*)&g_P0[rhi * 128 + cc] = o;
            }
        }
    }
}
#undef STAGE0
#undef KCH

// -- spmm width 128 + fused relu(AM⊙s + b0): H0 -> g_S0 --
__global__ void __launch_bounds__(256) k_spmm128(const float* __restrict__ AM,
                                                 const float* __restrict__ b0) {
    int w = (blockIdx.x * 256 + threadIdx.x) >> 5;
    int lane = threadIdx.x & 31;
    if (w >= NN) return;
    int s = g_rp[w], e = g_rp[w + 1];
    float4 acc = make_float4(0.f, 0.f, 0.f, 0.f);
    const float4* Xv = (const float4*)g_P0;
    int j = s;
    for (; j + 1 < e; j += 2) {
        int c0 = g_colP[j], c1 = g_colP[j + 1];
        float v0 = g_vZ[j], v1 = g_vZ[j + 1];
        float4 a = Xv[c0 * 32 + lane];
        float4 b = Xv[c1 * 32 + lane];
        acc.x += v0 * a.x + v1 * b.x;
        acc.y += v0 * a.y + v1 * b.y;
        acc.z += v0 * a.z + v1 * b.z;
        acc.w += v0 * a.w + v1 * b.w;
    }
    if (j < e) {
        int c = g_colP[j]; float v = g_vZ[j];
        float4 a = Xv[c * 32 + lane];
        acc.x += v * a.x; acc.y += v * a.y; acc.z += v * a.z; acc.w += v * a.w;
    }
    float am = AM[w];
    float4 bb = ((const float4*)b0)[lane];
    float4 o;
    o.x = fmaxf(fmaf(am, acc.x, bb.x), 0.f);
    o.y = fmaxf(fmaf(am, acc.y, bb.y), 0.f);
    o.z = fmaxf(fmaf(am, acc.z, bb.z), 0.f);
    o.w = fmaxf(fmaf(am, acc.w, bb.w), 0.f);
    ((float4*)g_S0)[w * 32 + lane] = o;
}

// ======== GEMM 1 (tf32, cp.async double-buffered): P1 = M ⊙ (H0 @ W1) ========
#define KCH1 16
__global__ void __launch_bounds__(256, 2) k_gemm1(const float* __restrict__ W1,
                                                  const float* __restrict__ M) {
    __shared__ __align__(16) float As[2][128 * 20];
    __shared__ __align__(16) float Bs[2][KCH1 * 64];
    int r0 = blockIdx.x * 128;
    int tid = threadIdx.x;
    int lane = tid & 31, wid = tid >> 5;
    int m0w = (wid & 3) * 32;
    int n0w = (wid >> 2) * 32;
    int g = lane >> 2, t = lane & 3;

    float acc[2][4][4];
    #pragma unroll
    for (int i = 0; i < 2; ++i)
        #pragma unroll
        for (int j = 0; j < 4; ++j)
            #pragma unroll
            for (int c = 0; c < 4; ++c) acc[i][j][c] = 0.f;

    const float4* hv = (const float4*)g_S0;
    const float4* wv = (const float4*)W1;

    int a_rr = tid >> 2, a_c4 = tid & 3;
    int b_kr = tid >> 4, b_c4 = tid & 15;

#define STAGE1(kc, buf)                                                          \
    {                                                                            \
        int _gr0 = r0 + a_rr;                                                    \
        int _gr1 = _gr0 + 64;                                                    \
        cp_async16(&As[buf][a_rr * 20 + a_c4 * 4],                               \
                   hv + (long)_gr0 * 32 + ((kc) >> 2) + a_c4,                    \
                   _gr0 < NN ? 16 : 0);                                          \
        cp_async16(&As[buf][(a_rr + 64) * 20 + a_c4 * 4],                        \
                   hv + (long)_gr1 * 32 + ((kc) >> 2) + a_c4,                    \
                   _gr1 < NN ? 16 : 0);                                          \
        cp_async16(&Bs[buf][b_kr * 64 + ((b_c4 * 4) ^ ((b_kr & 3) << 3))],       \
                   wv + ((kc) + b_kr) * 16 + b_c4, 16);                          \
        cp_commit();                                                             \
    }

    STAGE1(0, 0);
    cp_wait0();
    __syncthreads();

    int buf = 0;
    for (int kc = 0; kc < 128; kc += KCH1, buf ^= 1) {
        if (kc + KCH1 < 128) STAGE1(kc + KCH1, buf ^ 1);
        #pragma unroll
        for (int k8 = 0; k8 < KCH1; k8 += 8) {
            unsigned af[2][4], bf[4][2];
            #pragma unroll
            for (int mt = 0; mt < 2; ++mt) {
                int m = m0w + mt * 16 + g;
                af[mt][0] = f2tf(As[buf][m * 20 + k8 + t]);
                af[mt][1] = f2tf(As[buf][(m + 8) * 20 + k8 + t]);
                af[mt][2] = f2tf(As[buf][m * 20 + k8 + t + 4]);
                af[mt][3] = f2tf(As[buf][(m + 8) * 20 + k8 + t + 4]);
            }
            #pragma unroll
            for (int nt = 0; nt < 4; ++nt) {
                int n = n0w + nt * 8 + g;
                bf[nt][0] = f2tf(Bs[buf][(k8 + t) * 64 + (n ^ (t << 3))]);
                bf[nt][1] = f2tf(Bs[buf][(k8 + t + 4) * 64 + (n ^ (t << 3))]);
            }
            #pragma unroll
            for (int mt = 0; mt < 2; ++mt)
                #pragma unroll
                for (int nt = 0; nt < 4; ++nt)
                    mma_tf32(acc[mt][nt], af[mt], bf[nt]);
        }
        if (kc + KCH1 < 128) cp_wait0();
        __syncthreads();
    }

    #pragma unroll
    for (int mt = 0; mt < 2; ++mt) {
        int rlo = r0 + m0w + mt * 16 + g;
        int rhi = rlo + 8;
        float mlo = (rlo < NN) ? M[rlo] : 0.f;
        float mhi = (rhi < NN) ? M[rhi] : 0.f;
        #pragma unroll
        for (int nt = 0; nt < 4; ++nt) {
            int cc = n0w + nt * 8 + 2 * t;
            if (rlo < NN) {
                float2 o; o.x = mlo * acc[mt][nt][0]; o.y = mlo * acc[mt][nt][1];
                *(float2*)&g_P1[rlo * 64 + cc] = o;
            }
            if (rhi < NN) {
                float2 o; o.x = mhi * acc[mt][nt][2]; o.y = mhi * acc[mt][nt][3];
                *(float2*)&g_P1[rhi * 64 + cc] = o;
            }
        }
    }
}
#undef STAGE1
#undef KCH1

// -- spmm width 64 + fused relu(AM⊙s + b1): H1 -> g_S1 --
__global__ void __launch_bounds__(256) k_spmm64(const float* __restrict__ AM,
                                                const float* __restrict__ b1) {
    int w = (blockIdx.x * 256 + threadIdx.x) >> 5;
    int lane = threadIdx.x & 31;
    if (w >= NN) return;
    int s = g_rp[w], e = g_rp[w + 1];
    float ax = 0.f, ay = 0.f;
    const float2* Xv = (const float2*)g_P1;
    int j = s;
    for (; j + 1 < e; j += 2) {
        int c0 = g_colP[j], c1 = g_colP[j + 1];
        float v0 = g_vZ[j], v1 = g_vZ[j + 1];
        float2 a = Xv[c0 * 32 + lane];
        float2 b = Xv[c1 * 32 + lane];
        ax += v0 * a.x + v1 * b.x;
        ay += v0 * a.y + v1 * b.y;
    }
    if (j < e) {
        int c = g_colP[j]; float v = g_vZ[j];
        float2 a = Xv[c * 32 + lane];
        ax += v * a.x; ay += v * a.y;
    }
    float am = AM[w];
    float2 bb = ((const float2*)b1)[lane];
    float2 o;
    o.x = fmaxf(fmaf(am, ax, bb.x), 0.f);
    o.y = fmaxf(fmaf(am, ay, bb.y), 0.f);
    ((float2*)g_S1)[w * 32 + lane] = o;
}

// ------- GEMM 2: P2 = H1 @ W2, K=64, NO=40 (scalar; H1 pre-activated) -------
__global__ void __launch_bounds__(256) k_gemm2(const float* __restrict__ W2) {
    __shared__ float Xs[32][68];
    __shared__ float Ws[64 * 40];
    int r0 = blockIdx.x * 32;
    int tid = threadIdx.x;
    const float4* sv4 = (const float4*)g_S1;
    for (int i = tid; i < 512; i += 256) {
        int rr = i >> 4, c4 = i & 15;
        int gr = r0 + rr;
        float4 v = (gr < NN) ? sv4[gr * 16 + c4] : make_float4(0.f, 0.f, 0.f, 0.f);
        Xs[rr][c4 * 4 + 0] = v.x;
        Xs[rr][c4 * 4 + 1] = v.y;
        Xs[rr][c4 * 4 + 2] = v.z;
        Xs[rr][c4 * 4 + 3] = v.w;
    }
    for (int i = tid; i < 64 * 40; i += 256) Ws[i] = W2[i];
    __syncthreads();
    int row = tid >> 3, cg = tid & 7;
    float acc[5] = {0.f, 0.f, 0.f, 0.f, 0.f};
    #pragma unroll 4
    for (int k = 0; k < 64; ++k) {
        float xv = Xs[row][k];
        #pragma unroll
        for (int j = 0; j < 5; ++j) acc[j] += xv * Ws[k * 40 + cg * 5 + j];
    }
    int gr = r0 + row;
    if (gr < NN) {
        #pragma unroll
        for (int j = 0; j < 5; ++j) g_P2[gr * 40 + cg * 5 + j] = acc[j];
    }
}

// -- spmm width 40 on adj + b2 + fused log_softmax -> out; re-zeros g_deg --
__global__ void __launch_bounds__(256) k_spmm40_lsm(const float* __restrict__ b2,
                                                    float* __restrict__ out) {
    int gi = blockIdx.x * 256 + threadIdx.x;
    if (gi < NN) g_deg[gi] = 0;   // cleanup for next call/replay
    int w = gi >> 5;
    int lane = threadIdx.x & 31;
    if (w >= NN) return;
    int s = g_rp[w], e = g_rp[w + 1];
    bool act = lane < 20;
    float ax = 0.f, ay = 0.f;
    int j = s;
    for (; j + 1 < e; j += 2) {
        int c0 = g_colP[j], c1 = g_colP[j + 1];
        float v0 = g_vA[j], v1 = g_vA[j + 1];
        if (act) {
            float2 a = *(const float2*)&g_P2[c0 * 40 + 2 * lane];
            float2 b = *(const float2*)&g_P2[c1 * 40 + 2 * lane];
            ax += v0 * a.x + v1 * b.x;
            ay += v0 * a.y + v1 * b.y;
        }
    }
    if (j < e) {
        int c = g_colP[j];
        float v = g_vA[j];
        if (act) {
            float2 a = *(const float2*)&g_P2[c * 40 + 2 * lane];
            ax += v * a.x;
            ay += v * a.y;
        }
    }
    if (act) {
        ax += b2[2 * lane];
        ay += b2[2 * lane + 1];
    }
    float m = act ? fmaxf(ax, ay) : -INFINITY;
    for (int off = 16; off; off >>= 1) m = fmaxf(m, __shfl_xor_sync(0xffffffffu, m, off));
    float sum = act ? (expf(ax - m) + expf(ay - m)) : 0.f;
    for (int off = 16; off; off >>= 1) sum += __shfl_xor_sync(0xffffffffu, sum, off);
    float lse = m + logf(sum);
    if (act) {
        float2 o;
        o.x = ax - lse;
        o.y = ay - lse;
        *(float2*)&out[w * 40 + 2 * lane] = o;
    }
}

// ---------------- launch ----------------
extern "C" void kernel_launch(void* const* d_in, const int* in_sizes, int n_in,
                              void* d_out, int out_size) {
    const float* x    = (const float*)d_in[0];
    const float* M    = (const float*)d_in[1];
    const float* AM   = (const float*)d_in[2];
    const float* adjv = (const float*)d_in[3];
    const float* adjZ = (const float*)d_in[4];
    const float* W0   = (const float*)d_in[5];
    const float* b0   = (const float*)d_in[6];
    const float* W1   = (const float*)d_in[7];
    const float* b1   = (const float*)d_in[8];
    const float* W2   = (const float*)d_in[9];
    const float* b2   = (const float*)d_in[10];
    const int*   row  = (const int*)d_in[11];
    const int*   col  = (const int*)d_in[12];
    float* out = (float*)d_out;

    (void)in_sizes; (void)n_in; (void)out_size;

    // 10 launches — identical structure to the proven 170.0 µs version;
    // only delta: cursor-seeded scatter (no g_rp load per edge).
    k_hist<<<(EE + 255) / 256, 256>>>(row);
    k_scan1<<<NCH, 256>>>();
    k_scan23<<<NCH, 1024>>>();
    k_gemm0<<<(NN + 127) / 128, 256>>>(x, W0, M);        // 4th launch (ncu slot)
    k_scatter<<<(EE + 255) / 256, 256>>>(row, col, adjZ, adjv);

    k_spmm128<<<(NN + 7) / 8, 256>>>(AM, b0);
    k_gemm1<<<(NN + 127) / 128, 256>>>(W1, M);
    k_spmm64<<<(NN + 7) / 8, 256>>>(AM, b1);
    k_gemm2<<<(NN + 31) / 32, 256>>>(W2);
    k_spmm40_lsm<<<(NN + 7) / 8, 256>>>(b2, out);
}